// round 14
// baseline (speedup 1.0000x reference)
#include <cuda_runtime.h>
#include <cuda_fp16.h>
#include <math.h>

#define DD 128
#define MAXN 100000
#define MAXE 1600000
#define NPARTMAX 512
#define SST 132                      // smem row stride in floats (full-K rows)
#define GEMM_SMEM (2 * 128 * SST * 4)   // 135168 B

// ---------------- scratch (device globals) ----------------
__device__ int    g_is64;
__device__ int    g_src [MAXE];
__device__ int    g_dst [MAXE];
__device__ float  g_dinv[MAXN];
__device__ int    g_cnt [MAXN];
__device__ int    g_off [MAXN];
__device__ int    g_cur [MAXN];
__device__ int    g_csr [MAXE];
__device__ int    g_part[NPARTMAX];
__device__ __half g_hwh[ (size_t)MAXN * DD ];   // fp16 pre-aggregation intermediate (UNSCALED)
__device__ float  g_x32[ (size_t)MAXN * DD ];   // tf32-rounded x
__device__ float  g_h0 [ (size_t)MAXN * DD ];   // tf32-rounded layer outputs
__device__ float  g_h1 [ (size_t)MAXN * DD ];
__device__ float  g_h2 [ (size_t)MAXN * DD ];
__device__ float  g_w32[ 3*128*128 + 128*512 ]; // tf32-rounded weights
#define W_LIN_OFF (3*128*128)

__device__ __forceinline__ const float* sel_in(int sel) {
    return sel == 0 ? g_x32 : (sel == 1 ? g_h0 : (sel == 2 ? g_h1 : g_h2));
}
__device__ __forceinline__ float* sel_out(int sel) {
    return sel == 0 ? g_h0 : (sel == 1 ? g_h1 : g_h2);
}

// tf32 round-to-nearest then mask
__device__ __forceinline__ float tfround(float f) {
    unsigned u = (__float_as_uint(f) + 0x1000u) & 0xFFFFE000u;
    return __uint_as_float(u);
}

// ---------------- edge dtype detect (parallel, 1 warp) ----------------
__global__ void detect_kernel(const void* ei, int n) {
    int i = threadIdx.x;
    long long v = ((const long long*)ei)[i];
    int ok = (v >= 0 && v < (long long)n) ? 1 : 0;
    unsigned m = __ballot_sync(0xFFFFFFFFu, ok);
    if (i == 0) g_is64 = (m == 0xFFFFFFFFu) ? 1 : 0;
}

// ---------------- prep: round weights / x to tf32 ----------------
__global__ void prep_w_kernel(const float* __restrict__ conv_w,
                              const float* __restrict__ lin_w) {
    int i = blockIdx.x * blockDim.x + threadIdx.x;
    if (i < 12288) {
        float4 f = ((const float4*)conv_w)[i];
        ((float4*)g_w32)[i] = make_float4(tfround(f.x), tfround(f.y), tfround(f.z), tfround(f.w));
    }
    if (i < 16384) {
        float4 f = ((const float4*)lin_w)[i];
        ((float4*)(g_w32 + W_LIN_OFF))[i] =
            make_float4(tfround(f.x), tfround(f.y), tfround(f.z), tfround(f.w));
    }
}

__global__ void prep_x_kernel(const float* __restrict__ x, int n) {
    int i = blockIdx.x * blockDim.x + threadIdx.x;
    if (i >= n * 32) return;
    float4 f = ((const float4*)x)[i];
    ((float4*)g_x32)[i] = make_float4(tfround(f.x), tfround(f.y), tfround(f.z), tfround(f.w));
}

__global__ void zero_kernel(int n) {
    int i = blockIdx.x * blockDim.x + threadIdx.x;
    if (i < n) { g_cnt[i] = 0; g_cur[i] = 0; }
}

__global__ void convert_hist_kernel(const void* ei, int ne, int n) {
    int e = blockIdx.x * blockDim.x + threadIdx.x;
    if (e >= ne) return;
    int s, d;
    if (g_is64) {
        const long long* p = (const long long*)ei;
        s = (int)p[e];
        d = (int)p[(size_t)ne + e];
    } else {
        const int* p = (const int*)ei;
        s = p[e];
        d = p[(size_t)ne + e];
    }
    if ((unsigned)s >= (unsigned)n) s = 0;
    if ((unsigned)d >= (unsigned)n) d = 0;
    g_src[e] = s;
    g_dst[e] = d;
    atomicAdd(&g_cnt[d], 1);
}

__global__ void scan1_kernel(int n) {
    __shared__ int sh[256];
    int tid = threadIdx.x;
    int i = blockIdx.x * 256 + tid;
    int v = (i < n) ? g_cnt[i] : 0;
    sh[tid] = v;
    __syncthreads();
#pragma unroll
    for (int d = 1; d < 256; d <<= 1) {
        int t = (tid >= d) ? sh[tid - d] : 0;
        __syncthreads();
        sh[tid] += t;
        __syncthreads();
    }
    if (i < n) g_off[i] = sh[tid] - v;
    if (tid == 255) g_part[blockIdx.x] = sh[255];
}

__global__ void scan2_kernel(int npart) {
    __shared__ int sh[NPARTMAX];
    int tid = threadIdx.x;
    int v = (tid < npart) ? g_part[tid] : 0;
    sh[tid] = v;
    __syncthreads();
#pragma unroll
    for (int d = 1; d < NPARTMAX; d <<= 1) {
        int t = (tid >= d) ? sh[tid - d] : 0;
        __syncthreads();
        sh[tid] += t;
        __syncthreads();
    }
    if (tid < npart) g_part[tid] = sh[tid] - v;
}

__global__ void scan3_kernel(int n) {
    int i = blockIdx.x * blockDim.x + threadIdx.x;
    if (i < n) {
        g_off[i] += g_part[i >> 8];
        g_dinv[i] = rsqrtf((float)(g_cnt[i] + 1));
    }
}

__global__ void fill_kernel(int ne) {
    int e = blockIdx.x * blockDim.x + threadIdx.x;
    if (e < ne) {
        int d = g_dst[e];
        int p = g_off[d] + atomicAdd(&g_cur[d], 1);
        g_csr[p] = g_src[e];
    }
}

// ---------------- cp.async helpers ----------------
__device__ __forceinline__ void cpa16(unsigned dst, const void* src, int szb) {
    asm volatile("cp.async.cg.shared.global [%0], [%1], 16, %2;\n"
                 :: "r"(dst), "l"(src), "r"(szb));
}
__device__ __forceinline__ void cpa_commit() {
    asm volatile("cp.async.commit_group;\n" ::: "memory");
}
template<int N>
__device__ __forceinline__ void cpa_wait() {
    asm volatile("cp.async.wait_group %0;\n" :: "n"(N) : "memory");
}

__device__ __forceinline__ void mma1688_tf32(float* d, unsigned a0, unsigned a1,
                                             unsigned a2, unsigned a3,
                                             unsigned b0, unsigned b1) {
    asm volatile(
        "mma.sync.aligned.m16n8k8.row.col.f32.tf32.tf32.f32 "
        "{%0,%1,%2,%3}, {%4,%5,%6,%7}, {%8,%9}, {%0,%1,%2,%3};\n"
        : "+f"(d[0]), "+f"(d[1]), "+f"(d[2]), "+f"(d[3])
        : "r"(a0), "r"(a1), "r"(a2), "r"(a3), "r"(b0), "r"(b1));
}

// ============== tensor-core GEMM (tf32): full-K resident, barrier-free mainloop ==============
// CTA tile 128x128, full K=128 per source in smem. 512 threads / 16 warps, 32x32 warp tiles.
// Two cp.async halves per source (64 floats/row each): half = 2048 16B-segments per operand,
// 4 iterations x 512 threads. Compute runs barrier-free within each half.
// mode 0: C = A @ Wl^T -> g_hwh (fp16, UNSCALED)
// mode 1: C = concat(x,h0,h1,h2) @ lin_w^T + lin_b -> out (fp32)
__global__ __launch_bounds__(512, 1) void gemm_tc_kernel(
    const float* __restrict__ lb,
    float* __restrict__ outp,
    int layer, int mode, int n)
{
    extern __shared__ float sm[];
    float* smA = sm;
    float* smW = sm + 128 * SST;

    int row0 = blockIdx.x * 128;
    int t    = threadIdx.x;
    int warp = t >> 5;
    int lane = t & 31;
    int g    = lane >> 2;
    int t4   = lane & 3;
    int warp_m = warp & 3;    // 4 row groups of 32
    int warp_n = warp >> 2;   // 4 col groups of 32

    unsigned sA_b = (unsigned)__cvta_generic_to_shared(smA);
    unsigned sW_b = (unsigned)__cvta_generic_to_shared(smW);

    float acc[2][4][4];
#pragma unroll
    for (int a = 0; a < 2; a++)
#pragma unroll
        for (int b = 0; b < 4; b++)
#pragma unroll
            for (int c = 0; c < 4; c++) acc[a][b][c] = 0.f;

    const int nsrc = (mode == 0) ? 1 : 4;
    const int wstride = (mode == 0) ? DD : 512;
    const float* wsrc = (mode == 0) ? (g_w32 + (size_t)layer * DD * DD)
                                    : (g_w32 + W_LIN_OFF);

#define GHALF(Ap, kw, ph) do {                                                   \
        int kb = (ph) * 64;                                                      \
        _Pragma("unroll")                                                        \
        for (int v = 0; v < 4; v++) {                                            \
            int seg  = t + v * 512;                                              \
            int row  = seg >> 4;                                                 \
            int part = seg & 15;                                                 \
            int gr2  = row0 + row;                                               \
            unsigned so = (unsigned)(row * SST + kb + part * 4) * 4u;            \
            const float* asrc = (Ap) + (size_t)(gr2 < n ? gr2 : 0) * DD + kb + part * 4; \
            cpa16(sA_b + so, asrc, gr2 < n ? 16 : 0);                            \
            const float* wsp = wsrc + (size_t)row * wstride + (kw) + kb + part * 4; \
            cpa16(sW_b + so, wsp, 16);                                           \
        }                                                                        \
        cpa_commit();                                                            \
    } while (0)

    for (int s = 0; s < nsrc; s++) {
        if (s > 0) __syncthreads();   // prior source reads complete before overwrite

        const float* Ap = (mode == 0) ? sel_in(layer) : sel_in(s);
        int kw = (mode == 0) ? 0 : s * DD;

        GHALF(Ap, kw, 0);
        GHALF(Ap, kw, 1);

        for (int ph = 0; ph < 2; ph++) {
            if (ph == 0) cpa_wait<1>(); else cpa_wait<0>();
            __syncthreads();

#pragma unroll
            for (int gi = 0; gi < 8; gi++) {
                int grp = ph * 8 + gi;
                unsigned a0[2], a1[2], a2[2], a3[2];
#pragma unroll
                for (int mt = 0; mt < 2; mt++) {
                    int r0 = warp_m * 32 + mt * 16;
                    a0[mt] = __float_as_uint(smA[(r0 + g) * SST + grp * 8 + t4]);
                    a1[mt] = __float_as_uint(smA[(r0 + 8 + g) * SST + grp * 8 + t4]);
                    a2[mt] = __float_as_uint(smA[(r0 + g) * SST + grp * 8 + t4 + 4]);
                    a3[mt] = __float_as_uint(smA[(r0 + 8 + g) * SST + grp * 8 + t4 + 4]);
                }
#pragma unroll
                for (int j = 0; j < 4; j++) {
                    int cr = warp_n * 32 + j * 8 + g;
                    unsigned b0 = __float_as_uint(smW[cr * SST + grp * 8 + t4]);
                    unsigned b1 = __float_as_uint(smW[cr * SST + grp * 8 + t4 + 4]);
#pragma unroll
                    for (int mt = 0; mt < 2; mt++)
                        mma1688_tf32(acc[mt][j], a0[mt], a1[mt], a2[mt], a3[mt], b0, b1);
                }
            }
        }
    }
#undef GHALF

    // epilogue
#pragma unroll
    for (int mt = 0; mt < 2; mt++) {
        int gr0 = row0 + warp_m * 32 + mt * 16 + g;
        int gr1 = gr0 + 8;
        if (mode == 0) {
#pragma unroll
            for (int j = 0; j < 4; j++) {
                int col = warp_n * 32 + j * 8 + 2 * t4;
                if (gr0 < n)
                    *(__half2*)&g_hwh[(size_t)gr0 * DD + col] =
                        __floats2half2_rn(acc[mt][j][0], acc[mt][j][1]);
                if (gr1 < n)
                    *(__half2*)&g_hwh[(size_t)gr1 * DD + col] =
                        __floats2half2_rn(acc[mt][j][2], acc[mt][j][3]);
            }
        } else {
#pragma unroll
            for (int j = 0; j < 4; j++) {
                int col = warp_n * 32 + j * 8 + 2 * t4;
                float2 bb = *(const float2*)&lb[col];
                if (gr0 < n) {
                    float2 v = make_float2(acc[mt][j][0] + bb.x, acc[mt][j][1] + bb.y);
                    *(float2*)&outp[(size_t)gr0 * DD + col] = v;
                }
                if (gr1 < n) {
                    float2 v = make_float2(acc[mt][j][2] + bb.x, acc[mt][j][3] + bb.y);
                    *(float2*)&outp[(size_t)gr1 * DD + col] = v;
                }
            }
        }
    }
}

// ---------------- fp16 row gather: 4 halves per lane ----------------
__device__ __forceinline__ float4 ld_hw4(int row, int lane) {
    uint2 u = ((const uint2*)g_hwh)[(size_t)row * 32 + lane];
    float2 f0 = __half22float2(*(const __half2*)&u.x);
    float2 f1 = __half22float2(*(const __half2*)&u.y);
    return make_float4(f0.x, f0.y, f1.x, f1.y);
}

// ------- fused aggregate (applies dinv) + bias + ELU + residual; tf32-rounded output -------
__global__ void aggregate_kernel(const float* __restrict__ conv_b,
                                 int layer, int n)
{
    int w = (blockIdx.x * blockDim.x + threadIdx.x) >> 5;
    if (w >= n) return;
    int lane = threadIdx.x & 31;

    const float* hin = sel_in(layer);
    float* hout = sel_out(layer);
    const float* b = conv_b + (size_t)layer * DD;

    float dv = g_dinv[w];
    float4 sv = ld_hw4(w, lane);
    float4 a0 = make_float4(sv.x * dv, sv.y * dv, sv.z * dv, sv.w * dv);
    float4 a1 = make_float4(0.f, 0.f, 0.f, 0.f);
    float4 a2 = make_float4(0.f, 0.f, 0.f, 0.f);
    float4 a3 = make_float4(0.f, 0.f, 0.f, 0.f);

    int j   = g_off[w];
    int end = j + g_cnt[w];
    for (; j + 4 <= end; j += 4) {
        int s0 = g_csr[j], s1 = g_csr[j + 1], s2 = g_csr[j + 2], s3 = g_csr[j + 3];
        float d0 = g_dinv[s0], d1 = g_dinv[s1], d2 = g_dinv[s2], d3 = g_dinv[s3];
        float4 v0 = ld_hw4(s0, lane);
        float4 v1 = ld_hw4(s1, lane);
        float4 v2 = ld_hw4(s2, lane);
        float4 v3 = ld_hw4(s3, lane);
        a0.x = fmaf(v0.x, d0, a0.x); a0.y = fmaf(v0.y, d0, a0.y);
        a0.z = fmaf(v0.z, d0, a0.z); a0.w = fmaf(v0.w, d0, a0.w);
        a1.x = fmaf(v1.x, d1, a1.x); a1.y = fmaf(v1.y, d1, a1.y);
        a1.z = fmaf(v1.z, d1, a1.z); a1.w = fmaf(v1.w, d1, a1.w);
        a2.x = fmaf(v2.x, d2, a2.x); a2.y = fmaf(v2.y, d2, a2.y);
        a2.z = fmaf(v2.z, d2, a2.z); a2.w = fmaf(v2.w, d2, a2.w);
        a3.x = fmaf(v3.x, d3, a3.x); a3.y = fmaf(v3.y, d3, a3.y);
        a3.z = fmaf(v3.z, d3, a3.z); a3.w = fmaf(v3.w, d3, a3.w);
    }
    for (; j < end; j++) {
        int s0 = g_csr[j];
        float d0 = g_dinv[s0];
        float4 v0 = ld_hw4(s0, lane);
        a0.x = fmaf(v0.x, d0, a0.x); a0.y = fmaf(v0.y, d0, a0.y);
        a0.z = fmaf(v0.z, d0, a0.z); a0.w = fmaf(v0.w, d0, a0.w);
    }

    float4 bb = ((const float4*)b)[lane];
    float4 hi = ((const float4*)hin)[(size_t)w * 32 + lane];
    float4 o;
    float x0 = (a0.x + a1.x + a2.x + a3.x) * dv + bb.x; o.x = (x0 > 0.f ? x0 : expm1f(x0)) + hi.x;
    float x1 = (a0.y + a1.y + a2.y + a3.y) * dv + bb.y; o.y = (x1 > 0.f ? x1 : expm1f(x1)) + hi.y;
    float x2 = (a0.z + a1.z + a2.z + a3.z) * dv + bb.z; o.z = (x2 > 0.f ? x2 : expm1f(x2)) + hi.z;
    float x3 = (a0.w + a1.w + a2.w + a3.w) * dv + bb.w; o.w = (x3 > 0.f ? x3 : expm1f(x3)) + hi.w;

    float4 ro = make_float4(tfround(o.x), tfround(o.y), tfround(o.z), tfround(o.w));
    ((float4*)hout)[(size_t)w * 32 + lane] = ro;
}

// ---------------- launch ----------------
extern "C" void kernel_launch(void* const* d_in, const int* in_sizes, int n_in,
                              void* d_out, int out_size)
{
    const float* x      = (const float*)d_in[0];
    const void*  ei     = d_in[1];
    const float* conv_w = (const float*)d_in[2];       // [3,128,128]
    const float* conv_b = (const float*)d_in[3];       // [3,128]
    const float* lin_w  = (const float*)d_in[4];       // [128,512]
    const float* lin_b  = (const float*)d_in[5];       // [128]
    float*       out    = (float*)d_out;

    int n = in_sizes[0] / DD;       // 100000
    int e = in_sizes[1] / 2;        // 1600000

    int nb_n  = (n + 255) / 256;
    int nb_e  = (e + 255) / 256;
    int npart = (n + 255) / 256;

    int gblocks    = (n + 127) / 128;
    int agg_blocks = (n * 32 + 255) / 256;

    cudaFuncSetAttribute(gemm_tc_kernel,
                         cudaFuncAttributeMaxDynamicSharedMemorySize, GEMM_SMEM);

    // launch index 3 is the profiler's sample slot -> conv GEMM layer 0
    detect_kernel      <<<1, 32>>>(ei, n);                               // 0
    prep_w_kernel      <<<64, 256>>>(conv_w, lin_w);                     // 1
    prep_x_kernel      <<<(n * 32 + 255) / 256, 256>>>(x, n);            // 2
    gemm_tc_kernel     <<<gblocks, 512, GEMM_SMEM>>>(nullptr, nullptr, 0, 0, n);  // 3 <- profiled
    zero_kernel        <<<nb_n, 256>>>(n);                               // 4
    convert_hist_kernel<<<nb_e, 256>>>(ei, e, n);                        // 5
    scan1_kernel       <<<npart, 256>>>(n);                              // 6
    scan2_kernel       <<<1, NPARTMAX>>>(npart);                         // 7
    scan3_kernel       <<<nb_n, 256>>>(n);                               // 8
    fill_kernel        <<<nb_e, 256>>>(e);                               // 9
    aggregate_kernel   <<<agg_blocks, 256>>>(conv_b, 0, n);              // 10

    for (int l = 1; l < 3; l++) {
        gemm_tc_kernel  <<<gblocks, 512, GEMM_SMEM>>>(nullptr, nullptr, l, 0, n);
        aggregate_kernel<<<agg_blocks, 256>>>(conv_b, l, n);
    }
    gemm_tc_kernel     <<<gblocks, 512, GEMM_SMEM>>>(lin_b, out, 0, 1, n);
}

// round 15
// speedup vs baseline: 1.2342x; 1.2342x over previous
#include <cuda_runtime.h>
#include <cuda_fp16.h>
#include <math.h>

#define DD 128
#define MAXN 100000
#define MAXE 1600000
#define NPARTMAX 512
#define SPH 24                 // smem row stride in halves (48B; conflict-free: 12g+t4 perm)
#define STAGEH (128*SPH)

// ---------------- scratch (device globals) ----------------
__device__ int    g_is64;
__device__ int    g_src [MAXE];
__device__ int    g_dst [MAXE];
__device__ float  g_dinv[MAXN];
__device__ int    g_cnt [MAXN];
__device__ int    g_off [MAXN];
__device__ int    g_cur [MAXN];
__device__ int    g_csr [MAXE];
__device__ int    g_part[NPARTMAX];
__device__ __half g_hwh[ (size_t)MAXN * DD ];   // fp16 pre-aggregation intermediate (UNSCALED)
__device__ __half g_x16[ (size_t)MAXN * DD ];   // fp16 x
__device__ __half g_h16_0[ (size_t)MAXN * DD ]; // fp16 layer outputs
__device__ __half g_h16_1[ (size_t)MAXN * DD ];
__device__ __half g_h16_2[ (size_t)MAXN * DD ];
__device__ __half g_w16[ 3*128*128 + 128*512 ]; // fp16 weights
#define W_LIN_OFF (3*128*128)

__device__ __forceinline__ const __half* sel_in16(int sel) {
    return sel == 0 ? g_x16 : (sel == 1 ? g_h16_0 : (sel == 2 ? g_h16_1 : g_h16_2));
}
__device__ __forceinline__ __half* sel_out16(int sel) {
    return sel == 0 ? g_h16_0 : (sel == 1 ? g_h16_1 : g_h16_2);
}

// ---------------- edge dtype detect (parallel, 1 warp) ----------------
__global__ void detect_kernel(const void* ei, int n) {
    int i = threadIdx.x;
    long long v = ((const long long*)ei)[i];
    int ok = (v >= 0 && v < (long long)n) ? 1 : 0;
    unsigned m = __ballot_sync(0xFFFFFFFFu, ok);
    if (i == 0) g_is64 = (m == 0xFFFFFFFFu) ? 1 : 0;
}

// ---------------- prep: convert weights / x to fp16 ----------------
__global__ void prep_w_kernel(const float* __restrict__ conv_w,
                              const float* __restrict__ lin_w) {
    int i = blockIdx.x * blockDim.x + threadIdx.x;
    if (i < 12288) {                          // 3*128*128 floats = 12288 float4
        float4 f = ((const float4*)conv_w)[i];
        __half2 p0 = __floats2half2_rn(f.x, f.y);
        __half2 p1 = __floats2half2_rn(f.z, f.w);
        ((uint2*)g_w16)[i] = make_uint2(*(unsigned*)&p0, *(unsigned*)&p1);
    }
    if (i < 16384) {                          // 128*512 floats = 16384 float4
        float4 f = ((const float4*)lin_w)[i];
        __half2 p0 = __floats2half2_rn(f.x, f.y);
        __half2 p1 = __floats2half2_rn(f.z, f.w);
        ((uint2*)(g_w16 + W_LIN_OFF))[i] = make_uint2(*(unsigned*)&p0, *(unsigned*)&p1);
    }
}

__global__ void prep_x_kernel(const float* __restrict__ x, int n) {
    int i = blockIdx.x * blockDim.x + threadIdx.x;   // over n*32 float4
    if (i >= n * 32) return;
    float4 f = ((const float4*)x)[i];
    __half2 p0 = __floats2half2_rn(f.x, f.y);
    __half2 p1 = __floats2half2_rn(f.z, f.w);
    ((uint2*)g_x16)[i] = make_uint2(*(unsigned*)&p0, *(unsigned*)&p1);
}

__global__ void zero_kernel(int n) {
    int i = blockIdx.x * blockDim.x + threadIdx.x;
    if (i < n) { g_cnt[i] = 0; g_cur[i] = 0; }
}

__global__ void convert_hist_kernel(const void* ei, int ne, int n) {
    int e = blockIdx.x * blockDim.x + threadIdx.x;
    if (e >= ne) return;
    int s, d;
    if (g_is64) {
        const long long* p = (const long long*)ei;
        s = (int)p[e];
        d = (int)p[(size_t)ne + e];
    } else {
        const int* p = (const int*)ei;
        s = p[e];
        d = p[(size_t)ne + e];
    }
    if ((unsigned)s >= (unsigned)n) s = 0;
    if ((unsigned)d >= (unsigned)n) d = 0;
    g_src[e] = s;
    g_dst[e] = d;
    atomicAdd(&g_cnt[d], 1);
}

__global__ void scan1_kernel(int n) {
    __shared__ int sh[256];
    int tid = threadIdx.x;
    int i = blockIdx.x * 256 + tid;
    int v = (i < n) ? g_cnt[i] : 0;
    sh[tid] = v;
    __syncthreads();
#pragma unroll
    for (int d = 1; d < 256; d <<= 1) {
        int t = (tid >= d) ? sh[tid - d] : 0;
        __syncthreads();
        sh[tid] += t;
        __syncthreads();
    }
    if (i < n) g_off[i] = sh[tid] - v;
    if (tid == 255) g_part[blockIdx.x] = sh[255];
}

__global__ void scan2_kernel(int npart) {
    __shared__ int sh[NPARTMAX];
    int tid = threadIdx.x;
    int v = (tid < npart) ? g_part[tid] : 0;
    sh[tid] = v;
    __syncthreads();
#pragma unroll
    for (int d = 1; d < NPARTMAX; d <<= 1) {
        int t = (tid >= d) ? sh[tid - d] : 0;
        __syncthreads();
        sh[tid] += t;
        __syncthreads();
    }
    if (tid < npart) g_part[tid] = sh[tid] - v;
}

__global__ void scan3_kernel(int n) {
    int i = blockIdx.x * blockDim.x + threadIdx.x;
    if (i < n) {
        g_off[i] += g_part[i >> 8];
        g_dinv[i] = rsqrtf((float)(g_cnt[i] + 1));
    }
}

__global__ void fill_kernel(int ne) {
    int e = blockIdx.x * blockDim.x + threadIdx.x;
    if (e < ne) {
        int d = g_dst[e];
        int p = g_off[d] + atomicAdd(&g_cur[d], 1);
        g_csr[p] = g_src[e];
    }
}

// ---------------- cp.async helpers ----------------
__device__ __forceinline__ void cpa16(unsigned dst, const void* src, int szb) {
    asm volatile("cp.async.cg.shared.global [%0], [%1], 16, %2;\n"
                 :: "r"(dst), "l"(src), "r"(szb));
}
__device__ __forceinline__ void cpa_commit() {
    asm volatile("cp.async.commit_group;\n" ::: "memory");
}
template<int N>
__device__ __forceinline__ void cpa_wait() {
    asm volatile("cp.async.wait_group %0;\n" :: "n"(N) : "memory");
}

__device__ __forceinline__ void mma16816_f16(float* d, unsigned a0, unsigned a1,
                                             unsigned a2, unsigned a3,
                                             unsigned b0, unsigned b1) {
    asm volatile(
        "mma.sync.aligned.m16n8k16.row.col.f32.f16.f16.f32 "
        "{%0,%1,%2,%3}, {%4,%5,%6,%7}, {%8,%9}, {%0,%1,%2,%3};\n"
        : "+f"(d[0]), "+f"(d[1]), "+f"(d[2]), "+f"(d[3])
        : "r"(a0), "r"(a1), "r"(a2), "r"(a3), "r"(b0), "r"(b1));
}

// ============== tensor-core GEMM (fp16 in, fp32 acc), cp.async two-stage pipeline ==============
// CTA tile 128x128, 256 threads / 8 warps, warp tile 32x64. k-chunk = 16 halves.
// mode 0: C = A @ Wl^T -> g_hwh (fp16, UNSCALED)
// mode 1: C = concat(x,h0,h1,h2) @ lin_w^T + lin_b -> out (fp32)
__global__ __launch_bounds__(256) void gemm_tc_kernel(
    const float* __restrict__ lb,
    float* __restrict__ outp,
    int layer, int mode, int n)
{
    __shared__ __half smA[2 * STAGEH];
    __shared__ __half smW[2 * STAGEH];

    int row0 = blockIdx.x * 128;
    int t    = threadIdx.x;
    int warp = t >> 5;
    int lane = t & 31;
    int g    = lane >> 2;
    int t4   = lane & 3;
    int warp_m = warp & 3;    // 4 row groups of 32
    int warp_n = warp >> 2;   // 2 col groups of 64

    unsigned sA_b = (unsigned)__cvta_generic_to_shared(smA);
    unsigned sW_b = (unsigned)__cvta_generic_to_shared(smW);

    float acc[2][8][4];
#pragma unroll
    for (int a = 0; a < 2; a++)
#pragma unroll
        for (int b = 0; b < 8; b++)
#pragma unroll
            for (int c = 0; c < 4; c++) acc[a][b][c] = 0.f;

    const int NC = (mode == 0) ? 8 : 32;
    const int wstrideH = (mode == 0) ? DD : 512;
    const __half* wsrc = (mode == 0) ? (g_w16 + (size_t)layer * DD * DD)
                                     : (g_w16 + W_LIN_OFF);

    // loader: one 16B segment (8 halves) per operand per thread per chunk
    int lrow  = t >> 1;     // 0..127
    int lhalf = t & 1;      // 0/1: halves offset lhalf*8
    int grow  = row0 + lrow;

#define GISSUE(cc, st) do {                                                        \
        int kb, kwb; const __half* Ap;                                             \
        if (mode == 0) { Ap = sel_in16(layer); kb = (cc) * 16; kwb = kb; }         \
        else { int ss = (cc) >> 3; Ap = sel_in16(ss); kb = ((cc) & 7) * 16;        \
               kwb = ss * DD + kb; }                                               \
        unsigned so = (unsigned)((st) * STAGEH + lrow * SPH) * 2u + lhalf * 16u;   \
        const __half* asrc = Ap + (size_t)(grow < n ? grow : 0) * DD + kb + lhalf * 8; \
        cpa16(sA_b + so, asrc, grow < n ? 16 : 0);                                 \
        const __half* wsp = wsrc + (size_t)lrow * wstrideH + kwb + lhalf * 8;      \
        cpa16(sW_b + so, wsp, 16);                                                 \
        cpa_commit();                                                              \
    } while (0)

    GISSUE(0, 0);

    for (int c = 0; c < NC; c++) {
        int cur = c & 1;
        if (c + 1 < NC) { GISSUE(c + 1, (c + 1) & 1); cpa_wait<1>(); }
        else            { cpa_wait<0>(); }
        __syncthreads();

        const __half* As = smA + cur * STAGEH;
        const __half* Ws = smW + cur * STAGEH;

        unsigned a0[2], a1[2], a2[2], a3[2];
#pragma unroll
        for (int mt = 0; mt < 2; mt++) {
            int r0 = warp_m * 32 + mt * 16;
            const __half* ra = As + (r0 + g) * SPH;
            const __half* rb = As + (r0 + 8 + g) * SPH;
            a0[mt] = *(const unsigned*)&ra[2 * t4];
            a1[mt] = *(const unsigned*)&rb[2 * t4];
            a2[mt] = *(const unsigned*)&ra[2 * t4 + 8];
            a3[mt] = *(const unsigned*)&rb[2 * t4 + 8];
        }
#pragma unroll
        for (int j = 0; j < 8; j++) {
            int cr = warp_n * 64 + j * 8 + g;
            const __half* rw = Ws + cr * SPH;
            unsigned b0 = *(const unsigned*)&rw[2 * t4];
            unsigned b1 = *(const unsigned*)&rw[2 * t4 + 8];
#pragma unroll
            for (int mt = 0; mt < 2; mt++)
                mma16816_f16(acc[mt][j], a0[mt], a1[mt], a2[mt], a3[mt], b0, b1);
        }
        __syncthreads();   // reads done before this stage is overwritten
    }
#undef GISSUE

    // epilogue
#pragma unroll
    for (int mt = 0; mt < 2; mt++) {
        int gr0 = row0 + warp_m * 32 + mt * 16 + g;
        int gr1 = gr0 + 8;
        if (mode == 0) {
#pragma unroll
            for (int j = 0; j < 8; j++) {
                int col = warp_n * 64 + j * 8 + 2 * t4;
                if (gr0 < n)
                    *(__half2*)&g_hwh[(size_t)gr0 * DD + col] =
                        __floats2half2_rn(acc[mt][j][0], acc[mt][j][1]);
                if (gr1 < n)
                    *(__half2*)&g_hwh[(size_t)gr1 * DD + col] =
                        __floats2half2_rn(acc[mt][j][2], acc[mt][j][3]);
            }
        } else {
#pragma unroll
            for (int j = 0; j < 8; j++) {
                int col = warp_n * 64 + j * 8 + 2 * t4;
                float2 bb = *(const float2*)&lb[col];
                if (gr0 < n) {
                    float2 v = make_float2(acc[mt][j][0] + bb.x, acc[mt][j][1] + bb.y);
                    *(float2*)&outp[(size_t)gr0 * DD + col] = v;
                }
                if (gr1 < n) {
                    float2 v = make_float2(acc[mt][j][2] + bb.x, acc[mt][j][3] + bb.y);
                    *(float2*)&outp[(size_t)gr1 * DD + col] = v;
                }
            }
        }
    }
}

// ---------------- fp16 row gather: 4 halves per lane ----------------
__device__ __forceinline__ float4 ld_h4(const __half* base, int row, int lane) {
    uint2 u = ((const uint2*)base)[(size_t)row * 32 + lane];
    float2 f0 = __half22float2(*(const __half2*)&u.x);
    float2 f1 = __half22float2(*(const __half2*)&u.y);
    return make_float4(f0.x, f0.y, f1.x, f1.y);
}

// ------- fused aggregate (applies dinv) + bias + ELU + residual; fp16 in/out -------
__global__ void aggregate_kernel(const float* __restrict__ conv_b,
                                 int layer, int n)
{
    int w = (blockIdx.x * blockDim.x + threadIdx.x) >> 5;
    if (w >= n) return;
    int lane = threadIdx.x & 31;

    const __half* hin = sel_in16(layer);
    __half* hout = sel_out16(layer);
    const float* b = conv_b + (size_t)layer * DD;

    float dv = g_dinv[w];
    float4 sv = ld_h4(g_hwh, w, lane);
    float4 a0 = make_float4(sv.x * dv, sv.y * dv, sv.z * dv, sv.w * dv);
    float4 a1 = make_float4(0.f, 0.f, 0.f, 0.f);
    float4 a2 = make_float4(0.f, 0.f, 0.f, 0.f);
    float4 a3 = make_float4(0.f, 0.f, 0.f, 0.f);

    int j   = g_off[w];
    int end = j + g_cnt[w];
    for (; j + 4 <= end; j += 4) {
        int s0 = g_csr[j], s1 = g_csr[j + 1], s2 = g_csr[j + 2], s3 = g_csr[j + 3];
        float d0 = g_dinv[s0], d1 = g_dinv[s1], d2 = g_dinv[s2], d3 = g_dinv[s3];
        float4 v0 = ld_h4(g_hwh, s0, lane);
        float4 v1 = ld_h4(g_hwh, s1, lane);
        float4 v2 = ld_h4(g_hwh, s2, lane);
        float4 v3 = ld_h4(g_hwh, s3, lane);
        a0.x = fmaf(v0.x, d0, a0.x); a0.y = fmaf(v0.y, d0, a0.y);
        a0.z = fmaf(v0.z, d0, a0.z); a0.w = fmaf(v0.w, d0, a0.w);
        a1.x = fmaf(v1.x, d1, a1.x); a1.y = fmaf(v1.y, d1, a1.y);
        a1.z = fmaf(v1.z, d1, a1.z); a1.w = fmaf(v1.w, d1, a1.w);
        a2.x = fmaf(v2.x, d2, a2.x); a2.y = fmaf(v2.y, d2, a2.y);
        a2.z = fmaf(v2.z, d2, a2.z); a2.w = fmaf(v2.w, d2, a2.w);
        a3.x = fmaf(v3.x, d3, a3.x); a3.y = fmaf(v3.y, d3, a3.y);
        a3.z = fmaf(v3.z, d3, a3.z); a3.w = fmaf(v3.w, d3, a3.w);
    }
    for (; j < end; j++) {
        int s0 = g_csr[j];
        float d0 = g_dinv[s0];
        float4 v0 = ld_h4(g_hwh, s0, lane);
        a0.x = fmaf(v0.x, d0, a0.x); a0.y = fmaf(v0.y, d0, a0.y);
        a0.z = fmaf(v0.z, d0, a0.z); a0.w = fmaf(v0.w, d0, a0.w);
    }

    float4 bb = ((const float4*)b)[lane];
    float4 hi = ld_h4(hin, w, lane);
    float4 o;
    float x0 = (a0.x + a1.x + a2.x + a3.x) * dv + bb.x; o.x = (x0 > 0.f ? x0 : expm1f(x0)) + hi.x;
    float x1 = (a0.y + a1.y + a2.y + a3.y) * dv + bb.y; o.y = (x1 > 0.f ? x1 : expm1f(x1)) + hi.y;
    float x2 = (a0.z + a1.z + a2.z + a3.z) * dv + bb.z; o.z = (x2 > 0.f ? x2 : expm1f(x2)) + hi.z;
    float x3 = (a0.w + a1.w + a2.w + a3.w) * dv + bb.w; o.w = (x3 > 0.f ? x3 : expm1f(x3)) + hi.w;

    __half2 p0 = __floats2half2_rn(o.x, o.y);
    __half2 p1 = __floats2half2_rn(o.z, o.w);
    ((uint2*)hout)[(size_t)w * 32 + lane] = make_uint2(*(unsigned*)&p0, *(unsigned*)&p1);
}

// ---------------- launch ----------------
extern "C" void kernel_launch(void* const* d_in, const int* in_sizes, int n_in,
                              void* d_out, int out_size)
{
    const float* x      = (const float*)d_in[0];
    const void*  ei     = d_in[1];
    const float* conv_w = (const float*)d_in[2];       // [3,128,128]
    const float* conv_b = (const float*)d_in[3];       // [3,128]
    const float* lin_w  = (const float*)d_in[4];       // [128,512]
    const float* lin_b  = (const float*)d_in[5];       // [128]
    float*       out    = (float*)d_out;

    int n = in_sizes[0] / DD;       // 100000
    int e = in_sizes[1] / 2;        // 1600000

    int nb_n  = (n + 255) / 256;
    int nb_e  = (e + 255) / 256;
    int npart = (n + 255) / 256;

    int gblocks    = (n + 127) / 128;
    int agg_blocks = (n * 32 + 255) / 256;

    // launch index 3 is the profiler's sample slot -> conv GEMM layer 0
    detect_kernel      <<<1, 32>>>(ei, n);                               // 0
    prep_w_kernel      <<<64, 256>>>(conv_w, lin_w);                     // 1
    prep_x_kernel      <<<(n * 32 + 255) / 256, 256>>>(x, n);            // 2
    gemm_tc_kernel     <<<gblocks, 256>>>(nullptr, nullptr, 0, 0, n);    // 3 <- profiled
    zero_kernel        <<<nb_n, 256>>>(n);                               // 4
    convert_hist_kernel<<<nb_e, 256>>>(ei, e, n);                        // 5
    scan1_kernel       <<<npart, 256>>>(n);                              // 6
    scan2_kernel       <<<1, NPARTMAX>>>(npart);                         // 7
    scan3_kernel       <<<nb_n, 256>>>(n);                               // 8
    fill_kernel        <<<nb_e, 256>>>(e);                               // 9
    aggregate_kernel   <<<agg_blocks, 256>>>(conv_b, 0, n);              // 10

    for (int l = 1; l < 3; l++) {
        gemm_tc_kernel  <<<gblocks, 256>>>(nullptr, nullptr, l, 0, n);
        aggregate_kernel<<<agg_blocks, 256>>>(conv_b, l, n);
    }
    gemm_tc_kernel     <<<gblocks, 256>>>(lin_b, out, 0, 1, n);
}

// round 16
// speedup vs baseline: 1.2826x; 1.0392x over previous
#include <cuda_runtime.h>
#include <cuda_fp16.h>
#include <math.h>

#define DD 128
#define MAXN 100000
#define MAXE 1600000
#define NPARTMAX 512
#define SPH 24                 // smem row stride in halves (48B; conflict-free)
#define STAGEH (128*SPH)       // halves per stage per operand (6KB)
#define NSTG 4

// ---------------- scratch (device globals) ----------------
__device__ int    g_is64;
__device__ int    g_src [MAXE];
__device__ int    g_dst [MAXE];
__device__ float  g_dinv[MAXN];
__device__ int    g_cnt [MAXN];
__device__ int    g_off [MAXN];
__device__ int    g_cur [MAXN];
__device__ int    g_csr [MAXE];
__device__ int    g_part[NPARTMAX];
__device__ __half g_hwh[ (size_t)MAXN * DD ];   // fp16 pre-aggregation intermediate (UNSCALED)
__device__ __half g_x16[ (size_t)MAXN * DD ];   // fp16 x
__device__ __half g_h16_0[ (size_t)MAXN * DD ]; // fp16 layer outputs
__device__ __half g_h16_1[ (size_t)MAXN * DD ];
__device__ __half g_h16_2[ (size_t)MAXN * DD ];
__device__ __half g_w16[ 3*128*128 + 128*512 ]; // fp16 weights
#define W_LIN_OFF (3*128*128)

__device__ __forceinline__ const __half* sel_in16(int sel) {
    return sel == 0 ? g_x16 : (sel == 1 ? g_h16_0 : (sel == 2 ? g_h16_1 : g_h16_2));
}
__device__ __forceinline__ __half* sel_out16(int sel) {
    return sel == 0 ? g_h16_0 : (sel == 1 ? g_h16_1 : g_h16_2);
}

// ---------------- fused prep: detect + zero + convert x/w to fp16 ----------------
__global__ void prep_all_kernel(const float* __restrict__ x,
                                const float* __restrict__ conv_w,
                                const float* __restrict__ lin_w,
                                const void* ei, int n) {
    int i = blockIdx.x * blockDim.x + threadIdx.x;
    if (blockIdx.x == 0 && threadIdx.x < 32) {
        long long v = ((const long long*)ei)[threadIdx.x];
        int ok = (v >= 0 && v < (long long)n) ? 1 : 0;
        unsigned m = __ballot_sync(0xFFFFFFFFu, ok);
        if (threadIdx.x == 0) g_is64 = (m == 0xFFFFFFFFu) ? 1 : 0;
    }
    if (i < n) { g_cnt[i] = 0; g_cur[i] = 0; }
    if (i < n * 32) {
        float4 f = ((const float4*)x)[i];
        __half2 p0 = __floats2half2_rn(f.x, f.y);
        __half2 p1 = __floats2half2_rn(f.z, f.w);
        ((uint2*)g_x16)[i] = make_uint2(*(unsigned*)&p0, *(unsigned*)&p1);
    }
    if (i < 12288) {
        float4 f = ((const float4*)conv_w)[i];
        __half2 p0 = __floats2half2_rn(f.x, f.y);
        __half2 p1 = __floats2half2_rn(f.z, f.w);
        ((uint2*)g_w16)[i] = make_uint2(*(unsigned*)&p0, *(unsigned*)&p1);
    }
    if (i < 16384) {
        float4 f = ((const float4*)lin_w)[i];
        __half2 p0 = __floats2half2_rn(f.x, f.y);
        __half2 p1 = __floats2half2_rn(f.z, f.w);
        ((uint2*)(g_w16 + W_LIN_OFF))[i] = make_uint2(*(unsigned*)&p0, *(unsigned*)&p1);
    }
}

__global__ void convert_hist_kernel(const void* ei, int ne, int n) {
    int e = blockIdx.x * blockDim.x + threadIdx.x;
    if (e >= ne) return;
    int s, d;
    if (g_is64) {
        const long long* p = (const long long*)ei;
        s = (int)p[e];
        d = (int)p[(size_t)ne + e];
    } else {
        const int* p = (const int*)ei;
        s = p[e];
        d = p[(size_t)ne + e];
    }
    if ((unsigned)s >= (unsigned)n) s = 0;
    if ((unsigned)d >= (unsigned)n) d = 0;
    g_src[e] = s;
    g_dst[e] = d;
    atomicAdd(&g_cnt[d], 1);
}

__global__ void scan1_kernel(int n) {
    __shared__ int sh[256];
    int tid = threadIdx.x;
    int i = blockIdx.x * 256 + tid;
    int v = (i < n) ? g_cnt[i] : 0;
    sh[tid] = v;
    __syncthreads();
#pragma unroll
    for (int d = 1; d < 256; d <<= 1) {
        int t = (tid >= d) ? sh[tid - d] : 0;
        __syncthreads();
        sh[tid] += t;
        __syncthreads();
    }
    if (i < n) g_off[i] = sh[tid] - v;
    if (tid == 255) g_part[blockIdx.x] = sh[255];
}

__global__ void scan2_kernel(int npart) {
    __shared__ int sh[NPARTMAX];
    int tid = threadIdx.x;
    int v = (tid < npart) ? g_part[tid] : 0;
    sh[tid] = v;
    __syncthreads();
#pragma unroll
    for (int d = 1; d < NPARTMAX; d <<= 1) {
        int t = (tid >= d) ? sh[tid - d] : 0;
        __syncthreads();
        sh[tid] += t;
        __syncthreads();
    }
    if (tid < npart) g_part[tid] = sh[tid] - v;
}

__global__ void scan3_kernel(int n) {
    int i = blockIdx.x * blockDim.x + threadIdx.x;
    if (i < n) {
        g_off[i] += g_part[i >> 8];
        g_dinv[i] = rsqrtf((float)(g_cnt[i] + 1));
    }
}

__global__ void fill_kernel(int ne) {
    int e = blockIdx.x * blockDim.x + threadIdx.x;
    if (e < ne) {
        int d = g_dst[e];
        int p = g_off[d] + atomicAdd(&g_cur[d], 1);
        g_csr[p] = g_src[e];
    }
}

// ---------------- cp.async helpers ----------------
__device__ __forceinline__ void cpa16(unsigned dst, const void* src, int szb) {
    asm volatile("cp.async.cg.shared.global [%0], [%1], 16, %2;\n"
                 :: "r"(dst), "l"(src), "r"(szb));
}
__device__ __forceinline__ void cpa_commit() {
    asm volatile("cp.async.commit_group;\n" ::: "memory");
}
template<int N>
__device__ __forceinline__ void cpa_wait() {
    asm volatile("cp.async.wait_group %0;\n" :: "n"(N) : "memory");
}

__device__ __forceinline__ void mma16816_f16(float* d, unsigned a0, unsigned a1,
                                             unsigned a2, unsigned a3,
                                             unsigned b0, unsigned b1) {
    asm volatile(
        "mma.sync.aligned.m16n8k16.row.col.f32.f16.f16.f32 "
        "{%0,%1,%2,%3}, {%4,%5,%6,%7}, {%8,%9}, {%0,%1,%2,%3};\n"
        : "+f"(d[0]), "+f"(d[1]), "+f"(d[2]), "+f"(d[3])
        : "r"(a0), "r"(a1), "r"(a2), "r"(a3), "r"(b0), "r"(b1));
}

// ============== tensor-core GEMM (fp16 in, fp32 acc), 4-stage cp.async pipeline ==============
// CTA tile 128x128, 256 threads / 8 warps, warp tile 32x64. k-chunk = 16 halves.
// One __syncthreads per chunk; empty commit groups keep the pending-count invariant.
// mode 0: C = A @ Wl^T -> g_hwh (fp16, UNSCALED)
// mode 1: C = concat(x,h0,h1,h2) @ lin_w^T + lin_b -> out (fp32)
__global__ __launch_bounds__(256) void gemm_tc_kernel(
    const float* __restrict__ lb,
    float* __restrict__ outp,
    int layer, int mode, int n)
{
    __shared__ __half smA[NSTG * STAGEH];   // 24 KB
    __shared__ __half smW[NSTG * STAGEH];   // 24 KB

    int row0 = blockIdx.x * 128;
    int t    = threadIdx.x;
    int warp = t >> 5;
    int lane = t & 31;
    int g    = lane >> 2;
    int t4   = lane & 3;
    int warp_m = warp & 3;    // 4 row groups of 32
    int warp_n = warp >> 2;   // 2 col groups of 64

    unsigned sA_b = (unsigned)__cvta_generic_to_shared(smA);
    unsigned sW_b = (unsigned)__cvta_generic_to_shared(smW);

    float acc[2][8][4];
#pragma unroll
    for (int a = 0; a < 2; a++)
#pragma unroll
        for (int b = 0; b < 8; b++)
#pragma unroll
            for (int c = 0; c < 4; c++) acc[a][b][c] = 0.f;

    const int NC = (mode == 0) ? 8 : 32;
    const int wstrideH = (mode == 0) ? DD : 512;
    const __half* wsrc = (mode == 0) ? (g_w16 + (size_t)layer * DD * DD)
                                     : (g_w16 + W_LIN_OFF);

    int lrow  = t >> 1;     // 0..127
    int lhalf = t & 1;      // 0/1
    int grow  = row0 + lrow;

#define GISSUE(cc, st) do {                                                        \
        int kb, kwb; const __half* Ap;                                             \
        if (mode == 0) { Ap = sel_in16(layer); kb = (cc) * 16; kwb = kb; }         \
        else { int ss = (cc) >> 3; Ap = sel_in16(ss); kb = ((cc) & 7) * 16;        \
               kwb = ss * DD + kb; }                                               \
        unsigned so = (unsigned)((st) * STAGEH + lrow * SPH) * 2u + lhalf * 16u;   \
        const __half* asrc = Ap + (size_t)(grow < n ? grow : 0) * DD + kb + lhalf * 8; \
        cpa16(sA_b + so, asrc, grow < n ? 16 : 0);                                 \
        const __half* wsp = wsrc + (size_t)lrow * wstrideH + kwb + lhalf * 8;      \
        cpa16(sW_b + so, wsp, 16);                                                 \
        cpa_commit();                                                              \
    } while (0)

    // prologue: 3 chunks in flight
    GISSUE(0, 0);
    GISSUE(1, 1);
    GISSUE(2, 2);

    for (int c = 0; c < NC; c++) {
        int cur = c & 3;
        cpa_wait<NSTG - 2>();   // pending always 3 before this -> chunk c complete
        __syncthreads();

        const __half* As = smA + cur * STAGEH;
        const __half* Ws = smW + cur * STAGEH;

        unsigned a0[2], a1[2], a2[2], a3[2];
#pragma unroll
        for (int mt = 0; mt < 2; mt++) {
            int r0 = warp_m * 32 + mt * 16;
            const __half* ra = As + (r0 + g) * SPH;
            const __half* rb = As + (r0 + 8 + g) * SPH;
            a0[mt] = *(const unsigned*)&ra[2 * t4];
            a1[mt] = *(const unsigned*)&rb[2 * t4];
            a2[mt] = *(const unsigned*)&ra[2 * t4 + 8];
            a3[mt] = *(const unsigned*)&rb[2 * t4 + 8];
        }
#pragma unroll
        for (int j = 0; j < 8; j++) {
            int cr = warp_n * 64 + j * 8 + g;
            const __half* rw = Ws + cr * SPH;
            unsigned b0 = *(const unsigned*)&rw[2 * t4];
            unsigned b1 = *(const unsigned*)&rw[2 * t4 + 8];
#pragma unroll
            for (int mt = 0; mt < 2; mt++)
                mma16816_f16(acc[mt][j], a0[mt], a1[mt], a2[mt], a3[mt], b0, b1);
        }

        // issue chunk c+3 into stage (c+3)&3 == (c-1)&3 (safe: all threads passed barrier c)
        if (c + 3 < NC) GISSUE(c + 3, (c + 3) & 3);
        else            cpa_commit();   // empty group keeps pending-count invariant
    }
#undef GISSUE

    // epilogue (regs only; no smem use -> no sync needed)
#pragma unroll
    for (int mt = 0; mt < 2; mt++) {
        int gr0 = row0 + warp_m * 32 + mt * 16 + g;
        int gr1 = gr0 + 8;
        if (mode == 0) {
#pragma unroll
            for (int j = 0; j < 8; j++) {
                int col = warp_n * 64 + j * 8 + 2 * t4;
                if (gr0 < n)
                    *(__half2*)&g_hwh[(size_t)gr0 * DD + col] =
                        __floats2half2_rn(acc[mt][j][0], acc[mt][j][1]);
                if (gr1 < n)
                    *(__half2*)&g_hwh[(size_t)gr1 * DD + col] =
                        __floats2half2_rn(acc[mt][j][2], acc[mt][j][3]);
            }
        } else {
#pragma unroll
            for (int j = 0; j < 8; j++) {
                int col = warp_n * 64 + j * 8 + 2 * t4;
                float2 bb = *(const float2*)&lb[col];
                if (gr0 < n) {
                    float2 v = make_float2(acc[mt][j][0] + bb.x, acc[mt][j][1] + bb.y);
                    *(float2*)&outp[(size_t)gr0 * DD + col] = v;
                }
                if (gr1 < n) {
                    float2 v = make_float2(acc[mt][j][2] + bb.x, acc[mt][j][3] + bb.y);
                    *(float2*)&outp[(size_t)gr1 * DD + col] = v;
                }
            }
        }
    }
}

// ---------------- fp16 row gather: 4 halves per lane ----------------
__device__ __forceinline__ float4 ld_h4(const __half* base, int row, int lane) {
    uint2 u = ((const uint2*)base)[(size_t)row * 32 + lane];
    float2 f0 = __half22float2(*(const __half2*)&u.x);
    float2 f1 = __half22float2(*(const __half2*)&u.y);
    return make_float4(f0.x, f0.y, f1.x, f1.y);
}

// ------- fused aggregate (applies dinv) + bias + ELU + residual; fp16 in/out -------
__global__ void aggregate_kernel(const float* __restrict__ conv_b,
                                 int layer, int n)
{
    int w = (blockIdx.x * blockDim.x + threadIdx.x) >> 5;
    if (w >= n) return;
    int lane = threadIdx.x & 31;

    const __half* hin = sel_in16(layer);
    __half* hout = sel_out16(layer);
    const float* b = conv_b + (size_t)layer * DD;

    float dv = g_dinv[w];
    float4 sv = ld_h4(g_hwh, w, lane);
    float4 a0 = make_float4(sv.x * dv, sv.y * dv, sv.z * dv, sv.w * dv);
    float4 a1 = make_float4(0.f, 0.f, 0.f, 0.f);
    float4 a2 = make_float4(0.f, 0.f, 0.f, 0.f);
    float4 a3 = make_float4(0.f, 0.f, 0.f, 0.f);

    int j   = g_off[w];
    int end = j + g_cnt[w];
    for (; j + 4 <= end; j += 4) {
        int s0 = g_csr[j], s1 = g_csr[j + 1], s2 = g_csr[j + 2], s3 = g_csr[j + 3];
        float d0 = g_dinv[s0], d1 = g_dinv[s1], d2 = g_dinv[s2], d3 = g_dinv[s3];
        float4 v0 = ld_h4(g_hwh, s0, lane);
        float4 v1 = ld_h4(g_hwh, s1, lane);
        float4 v2 = ld_h4(g_hwh, s2, lane);
        float4 v3 = ld_h4(g_hwh, s3, lane);
        a0.x = fmaf(v0.x, d0, a0.x); a0.y = fmaf(v0.y, d0, a0.y);
        a0.z = fmaf(v0.z, d0, a0.z); a0.w = fmaf(v0.w, d0, a0.w);
        a1.x = fmaf(v1.x, d1, a1.x); a1.y = fmaf(v1.y, d1, a1.y);
        a1.z = fmaf(v1.z, d1, a1.z); a1.w = fmaf(v1.w, d1, a1.w);
        a2.x = fmaf(v2.x, d2, a2.x); a2.y = fmaf(v2.y, d2, a2.y);
        a2.z = fmaf(v2.z, d2, a2.z); a2.w = fmaf(v2.w, d2, a2.w);
        a3.x = fmaf(v3.x, d3, a3.x); a3.y = fmaf(v3.y, d3, a3.y);
        a3.z = fmaf(v3.z, d3, a3.z); a3.w = fmaf(v3.w, d3, a3.w);
    }
    for (; j < end; j++) {
        int s0 = g_csr[j];
        float d0 = g_dinv[s0];
        float4 v0 = ld_h4(g_hwh, s0, lane);
        a0.x = fmaf(v0.x, d0, a0.x); a0.y = fmaf(v0.y, d0, a0.y);
        a0.z = fmaf(v0.z, d0, a0.z); a0.w = fmaf(v0.w, d0, a0.w);
    }

    float4 bb = ((const float4*)b)[lane];
    float4 hi = ld_h4(hin, w, lane);
    float4 o;
    float x0 = (a0.x + a1.x + a2.x + a3.x) * dv + bb.x; o.x = (x0 > 0.f ? x0 : expm1f(x0)) + hi.x;
    float x1 = (a0.y + a1.y + a2.y + a3.y) * dv + bb.y; o.y = (x1 > 0.f ? x1 : expm1f(x1)) + hi.y;
    float x2 = (a0.z + a1.z + a2.z + a3.z) * dv + bb.z; o.z = (x2 > 0.f ? x2 : expm1f(x2)) + hi.z;
    float x3 = (a0.w + a1.w + a2.w + a3.w) * dv + bb.w; o.w = (x3 > 0.f ? x3 : expm1f(x3)) + hi.w;

    __half2 p0 = __floats2half2_rn(o.x, o.y);
    __half2 p1 = __floats2half2_rn(o.z, o.w);
    ((uint2*)hout)[(size_t)w * 32 + lane] = make_uint2(*(unsigned*)&p0, *(unsigned*)&p1);
}

// ---------------- launch ----------------
extern "C" void kernel_launch(void* const* d_in, const int* in_sizes, int n_in,
                              void* d_out, int out_size)
{
    const float* x      = (const float*)d_in[0];
    const void*  ei     = d_in[1];
    const float* conv_w = (const float*)d_in[2];       // [3,128,128]
    const float* conv_b = (const float*)d_in[3];       // [3,128]
    const float* lin_w  = (const float*)d_in[4];       // [128,512]
    const float* lin_b  = (const float*)d_in[5];       // [128]
    float*       out    = (float*)d_out;

    int n = in_sizes[0] / DD;       // 100000
    int e = in_sizes[1] / 2;        // 1600000

    int nb_n  = (n + 255) / 256;
    int nb_e  = (e + 255) / 256;
    int npart = (n + 255) / 256;

    int gblocks    = (n + 127) / 128;
    int agg_blocks = (n * 32 + 255) / 256;

    // execution is serial (single capture stream) -> minimize total work.
    // launch index 3 is the profiler's sample slot -> conv GEMM layer 0
    prep_all_kernel    <<<(n * 32 + 255) / 256, 256>>>(x, conv_w, lin_w, ei, n); // 0
    convert_hist_kernel<<<nb_e, 256>>>(ei, e, n);                        // 1
    scan1_kernel       <<<npart, 256>>>(n);                              // 2
    gemm_tc_kernel     <<<gblocks, 256>>>(nullptr, nullptr, 0, 0, n);    // 3 <- profiled
    scan2_kernel       <<<1, NPARTMAX>>>(npart);                         // 4
    scan3_kernel       <<<nb_n, 256>>>(n);                               // 5
    fill_kernel        <<<nb_e, 256>>>(e);                               // 6
    aggregate_kernel   <<<agg_blocks, 256>>>(conv_b, 0, n);              // 7

    for (int l = 1; l < 3; l++) {
        gemm_tc_kernel  <<<gblocks, 256>>>(nullptr, nullptr, l, 0, n);
        aggregate_kernel<<<agg_blocks, 256>>>(conv_b, l, n);
    }
    gemm_tc_kernel     <<<gblocks, 256>>>(lin_b, out, 0, 1, n);
}